// round 1
// baseline (speedup 1.0000x reference)
#include <cuda_runtime.h>

#define BATCH 4
#define H 128
#define W 128
#define HW (H*W)
#define CIN_X 256
#define CSKIP 128
#define CCAT 384
#define COUT 128
#define NPIX (BATCH*HW)      // per-channel reduction size = 65536
#define EPSV 1e-5f

// ---------------- scratch (device globals; no allocations allowed) ----------
__device__ float g_cat[BATCH*CCAT*HW];   // concat(skip, upsampled x)
__device__ float g_h[BATCH*COUT*HW];     // conv1 out, then BN+ReLU in place
__device__ float g_off[BATCH*18*HW];     // offsets
__device__ float g_y[BATCH*COUT*HW];     // deform conv out (pre-BN)
__device__ float g_sum1[COUT], g_sq1[COUT], g_sum2[COUT], g_sq2[COUT];
__device__ float g_scale1[COUT], g_shift1[COUT], g_scale2[COUT], g_shift2[COUT];

// ---------------- kernel Z: zero the stats accumulators ---------------------
__global__ void k_zero() {
    int t = threadIdx.x;
    if (t < COUT) { g_sum1[t]=0.f; g_sq1[t]=0.f; g_sum2[t]=0.f; g_sq2[t]=0.f; }
}

// ---------------- kernel A: upsample(2x, align_corners) + concat ------------
__global__ void k_upcat(const float* __restrict__ x, const float* __restrict__ skip) {
    int idx = blockIdx.x * blockDim.x + threadIdx.x;
    if (idx >= BATCH*CCAT*HW) return;
    int xc = idx % W;
    int y  = (idx / W) % H;
    int c  = (idx / HW) % CCAT;
    int b  = idx / (HW*CCAT);
    float v;
    if (c < CSKIP) {
        v = skip[((b*CSKIP + c)*H + y)*W + xc];
    } else {
        int ci = c - CSKIP;
        const float* xp = x + (size_t)(b*CIN_X + ci)*(H/2)*(W/2);
        float fy = (float)y  * (63.0f / 127.0f);
        float fx = (float)xc * (63.0f / 127.0f);
        int y0 = (int)fy, x0 = (int)fx;      // coords >= 0, trunc == floor
        float wy = fy - (float)y0, wx = fx - (float)x0;
        int y1 = min(y0+1, 63), x1 = min(x0+1, 63);
        float v00 = xp[y0*64+x0], v01 = xp[y0*64+x1];
        float v10 = xp[y1*64+x0], v11 = xp[y1*64+x1];
        v = v00*(1.f-wy)*(1.f-wx) + v01*(1.f-wy)*wx + v10*wy*(1.f-wx) + v11*wy*wx;
    }
    g_cat[idx] = v;
}

// ---------------- kernel B: conv1 3x3 (384->128), accumulate BN1 stats ------
// tile: 32x16 pixels, 16 out-channels per block; thread = 2 px (y, y+8) x 16 oc
__global__ __launch_bounds__(256) void k_conv1(const float* __restrict__ w) {
    __shared__ float sIn[4][18][34];
    __shared__ float sW[4][9][16];
    __shared__ float sSum[16], sSq[16];
    int tid = threadIdx.x;
    int tx = tid & 31, tyq = tid >> 5;
    int tileX = blockIdx.x * 32, tileY = blockIdx.y * 16;
    int b = blockIdx.z >> 3, ocg = blockIdx.z & 7;
    int ocBase = ocg * 16;

    float acc0[16], acc1[16];
    #pragma unroll
    for (int i=0;i<16;i++){ acc0[i]=0.f; acc1[i]=0.f; }

    for (int c0 = 0; c0 < CCAT; c0 += 4) {
        for (int i = tid; i < 4*18*34; i += 256) {
            int ci = i / 612, r = i % 612, ly = r / 34, lx = r % 34;
            int gy = tileY + ly - 1, gx = tileX + lx - 1;
            float v = 0.f;
            if (gy >= 0 && gy < H && gx >= 0 && gx < W)
                v = g_cat[((b*CCAT + c0 + ci)*H + gy)*W + gx];
            sIn[ci][ly][lx] = v;
        }
        for (int i = tid; i < 4*9*16; i += 256) {
            int ci = i / 144, r = i % 144, tap = r / 16, oc = r % 16;
            sW[ci][tap][oc] = w[((ocBase+oc)*CCAT + c0 + ci)*9 + tap];
        }
        __syncthreads();
        #pragma unroll
        for (int ci = 0; ci < 4; ci++) {
            #pragma unroll
            for (int ky = 0; ky < 3; ky++) {
                #pragma unroll
                for (int kx = 0; kx < 3; kx++) {
                    float v0 = sIn[ci][tyq + ky][tx + kx];
                    float v1 = sIn[ci][tyq + 8 + ky][tx + kx];
                    #pragma unroll
                    for (int oc = 0; oc < 16; oc++) {
                        float wv = sW[ci][ky*3+kx][oc];
                        acc0[oc] += v0 * wv;
                        acc1[oc] += v1 * wv;
                    }
                }
            }
        }
        __syncthreads();
    }

    if (tid < 16) { sSum[tid] = 0.f; sSq[tid] = 0.f; }
    __syncthreads();
    int y0 = tileY + tyq, y1 = y0 + 8, xg = tileX + tx;
    #pragma unroll
    for (int oc = 0; oc < 16; oc++) {
        float a0 = acc0[oc], a1 = acc1[oc];
        g_h[((b*COUT + ocBase + oc)*H + y0)*W + xg] = a0;
        g_h[((b*COUT + ocBase + oc)*H + y1)*W + xg] = a1;
        atomicAdd(&sSum[oc], a0 + a1);
        atomicAdd(&sSq[oc], a0*a0 + a1*a1);
    }
    __syncthreads();
    if (tid < 16) {
        atomicAdd(&g_sum1[ocBase + tid], sSum[tid]);
        atomicAdd(&g_sq1[ocBase + tid], sSq[tid]);
    }
}

// ---------------- kernel C: finalize BN scale/shift --------------------------
__global__ void k_bnfin(int which, const float* __restrict__ g, const float* __restrict__ bb) {
    int c = threadIdx.x;
    if (c >= COUT) return;
    float s = which ? g_sum2[c] : g_sum1[c];
    float q = which ? g_sq2[c]  : g_sq1[c];
    float m = s / (float)NPIX;
    float v = q / (float)NPIX - m*m;
    float sc = g[c] * rsqrtf(v + EPSV);
    float sh = bb[c] - m * sc;
    if (which) { g_scale2[c] = sc; g_shift2[c] = sh; }
    else       { g_scale1[c] = sc; g_shift1[c] = sh; }
}

// ---------------- kernel D: BN1 + ReLU in place on g_h -----------------------
__global__ void k_bnrelu1() {
    int idx = blockIdx.x * 256 + threadIdx.x;
    if (idx >= BATCH*COUT*HW) return;
    int c = (idx / HW) % COUT;
    float v = g_h[idx] * g_scale1[c] + g_shift1[c];
    g_h[idx] = fmaxf(v, 0.f);
}

// ---------------- kernel E: offset conv 3x3 (128->18) + bias -----------------
__global__ __launch_bounds__(256) void k_offconv(const float* __restrict__ w,
                                                 const float* __restrict__ bias) {
    __shared__ float sIn[8][18][34];
    __shared__ float sW[8][9][18];
    int tid = threadIdx.x;
    int tx = tid & 31, tyq = tid >> 5;
    int tileX = blockIdx.x * 32, tileY = blockIdx.y * 16;
    int b = blockIdx.z;
    float acc0[18], acc1[18];
    #pragma unroll
    for (int i=0;i<18;i++){ acc0[i]=0.f; acc1[i]=0.f; }

    for (int c0 = 0; c0 < COUT; c0 += 8) {
        for (int i = tid; i < 8*18*34; i += 256) {
            int ci = i / 612, r = i % 612, ly = r / 34, lx = r % 34;
            int gy = tileY + ly - 1, gx = tileX + lx - 1;
            float v = 0.f;
            if (gy >= 0 && gy < H && gx >= 0 && gx < W)
                v = g_h[((b*COUT + c0 + ci)*H + gy)*W + gx];
            sIn[ci][ly][lx] = v;
        }
        for (int i = tid; i < 8*9*18; i += 256) {
            int ci = i / 162, r = i % 162, tap = r / 18, oc = r % 18;
            sW[ci][tap][oc] = w[(oc*COUT + c0 + ci)*9 + tap];
        }
        __syncthreads();
        #pragma unroll
        for (int ci = 0; ci < 8; ci++) {
            #pragma unroll
            for (int ky = 0; ky < 3; ky++) {
                #pragma unroll
                for (int kx = 0; kx < 3; kx++) {
                    float v0 = sIn[ci][tyq + ky][tx + kx];
                    float v1 = sIn[ci][tyq + 8 + ky][tx + kx];
                    #pragma unroll
                    for (int oc = 0; oc < 18; oc++) {
                        float wv = sW[ci][ky*3+kx][oc];
                        acc0[oc] += v0 * wv;
                        acc1[oc] += v1 * wv;
                    }
                }
            }
        }
        __syncthreads();
    }
    int y0 = tileY + tyq, y1 = y0 + 8, xg = tileX + tx;
    #pragma unroll
    for (int oc = 0; oc < 18; oc++) {
        float bv = bias[oc];
        g_off[((b*18 + oc)*H + y0)*W + xg] = acc0[oc] + bv;
        g_off[((b*18 + oc)*H + y1)*W + xg] = acc1[oc] + bv;
    }
}

// ---------------- kernel F: deformable conv (sample + 3x3 GEMM) + BN2 stats --
// tile: 32x4 = 128 pixels, 64 out-channels; thread = 4 px (row-strided) x 8 oc
__global__ __launch_bounds__(256) void k_deform(const float* __restrict__ dw,
                                                const float* __restrict__ db) {
    __shared__ float sGeo[4][128];    // y0f, x0f, wy, wx per pixel
    __shared__ float sS[8][128];      // sampled values [ci][px]
    __shared__ float sWk[64][8];      // weights for current (k, ci-chunk)
    __shared__ float sSum[64], sSq[64];
    int tid = threadIdx.x;
    int pxg = tid & 31, ocg = tid >> 5;
    int tileX = blockIdx.x * 32, tileY = blockIdx.y * 4;
    int b = blockIdx.z >> 1;
    int ocBase = (blockIdx.z & 1) * 64;

    float acc[4][8];
    #pragma unroll
    for (int p=0;p<4;p++)
        #pragma unroll
        for (int j=0;j<8;j++) acc[p][j]=0.f;

    for (int k = 0; k < 9; k++) {
        if (tid < 128) {
            int ly = tid >> 5, lx = tid & 31;
            int y = tileY + ly, x = tileX + lx;
            float dy = g_off[((b*18 + 2*k    )*H + y)*W + x];
            float dx = g_off[((b*18 + 2*k + 1)*H + y)*W + x];
            float py = (float)y + (float)(k/3 - 1) + dy;
            float px = (float)x + (float)(k%3 - 1) + dx;
            float y0 = floorf(py), x0 = floorf(px);
            sGeo[0][tid] = y0;
            sGeo[1][tid] = x0;
            sGeo[2][tid] = py - y0;
            sGeo[3][tid] = px - x0;
        }
        __syncthreads();
        for (int c0 = 0; c0 < COUT; c0 += 8) {
            #pragma unroll
            for (int i = 0; i < 4; i++) {
                int idx = tid + i*256;
                int ci = idx >> 7, p = idx & 127;
                float y0 = sGeo[0][p], x0 = sGeo[1][p];
                float wy = sGeo[2][p], wx = sGeo[3][p];
                int yi = (int)y0, xi = (int)x0;
                const float* hp = g_h + (size_t)(b*COUT + c0 + ci)*HW;
                float v00=0.f, v01=0.f, v10=0.f, v11=0.f;
                bool yv0 = (yi   >= 0) && (yi   < H);
                bool yv1 = (yi+1 >= 0) && (yi+1 < H);
                bool xv0 = (xi   >= 0) && (xi   < W);
                bool xv1 = (xi+1 >= 0) && (xi+1 < W);
                if (yv0 && xv0) v00 = hp[yi*W + xi];
                if (yv0 && xv1) v01 = hp[yi*W + xi + 1];
                if (yv1 && xv0) v10 = hp[(yi+1)*W + xi];
                if (yv1 && xv1) v11 = hp[(yi+1)*W + xi + 1];
                sS[ci][p] = v00*(1.f-wy)*(1.f-wx) + v01*(1.f-wy)*wx
                          + v10*wy*(1.f-wx)       + v11*wy*wx;
            }
            #pragma unroll
            for (int i = 0; i < 2; i++) {
                int idx = tid + i*256;
                int oc = idx >> 3, ci = idx & 7;
                sWk[oc][ci] = dw[((ocBase + oc)*COUT + c0 + ci)*9 + k];
            }
            __syncthreads();
            #pragma unroll
            for (int ci = 0; ci < 8; ci++) {
                float v[4];
                #pragma unroll
                for (int p = 0; p < 4; p++) v[p] = sS[ci][p*32 + pxg];
                #pragma unroll
                for (int j = 0; j < 8; j++) {
                    float wv = sWk[ocg*8 + j][ci];
                    #pragma unroll
                    for (int p = 0; p < 4; p++) acc[p][j] += v[p] * wv;
                }
            }
            __syncthreads();
        }
    }

    if (tid < 64) { sSum[tid] = 0.f; sSq[tid] = 0.f; }
    __syncthreads();
    int x = tileX + pxg;
    #pragma unroll
    for (int j = 0; j < 8; j++) {
        int ocl = ocg*8 + j;
        int oc = ocBase + ocl;
        float bias = db[oc];
        float ls = 0.f, lq = 0.f;
        #pragma unroll
        for (int p = 0; p < 4; p++) {
            int y = tileY + p;
            float v = acc[p][j] + bias;
            g_y[((b*COUT + oc)*H + y)*W + x] = v;
            ls += v; lq += v*v;
        }
        atomicAdd(&sSum[ocl], ls);
        atomicAdd(&sSq[ocl], lq);
    }
    __syncthreads();
    if (tid < 64) {
        atomicAdd(&g_sum2[ocBase + tid], sSum[tid]);
        atomicAdd(&g_sq2[ocBase + tid], sSq[tid]);
    }
}

// ---------------- kernel H: BN2 + ReLU -> d_out -------------------------------
__global__ void k_bnrelu2(float* __restrict__ out) {
    int idx = blockIdx.x * 256 + threadIdx.x;
    if (idx >= BATCH*COUT*HW) return;
    int c = (idx / HW) % COUT;
    float v = g_y[idx] * g_scale2[c] + g_shift2[c];
    out[idx] = fmaxf(v, 0.f);
}

// ---------------- launch ------------------------------------------------------
extern "C" void kernel_launch(void* const* d_in, const int* in_sizes, int n_in,
                              void* d_out, int out_size) {
    const float* x       = (const float*)d_in[0];
    const float* skip    = (const float*)d_in[1];
    const float* conv1_w = (const float*)d_in[2];
    const float* bn1_g   = (const float*)d_in[3];
    const float* bn1_b   = (const float*)d_in[4];
    const float* off_w   = (const float*)d_in[5];
    const float* off_b   = (const float*)d_in[6];
    const float* def_w   = (const float*)d_in[7];
    const float* def_b   = (const float*)d_in[8];
    const float* bn2_g   = (const float*)d_in[9];
    const float* bn2_b   = (const float*)d_in[10];
    float* out = (float*)d_out;

    k_zero<<<1, 256>>>();

    int ncat = BATCH*CCAT*HW;
    k_upcat<<<(ncat + 255)/256, 256>>>(x, skip);

    k_conv1<<<dim3(W/32, H/16, BATCH*8), 256>>>(conv1_w);
    k_bnfin<<<1, COUT>>>(0, bn1_g, bn1_b);

    int nh = BATCH*COUT*HW;
    k_bnrelu1<<<(nh + 255)/256, 256>>>();

    k_offconv<<<dim3(W/32, H/16, BATCH), 256>>>(off_w, off_b);

    k_deform<<<dim3(W/32, H/4, BATCH*2), 256>>>(def_w, def_b);
    k_bnfin<<<1, COUT>>>(1, bn2_g, bn2_b);

    k_bnrelu2<<<(nh + 255)/256, 256>>>(out);
}

// round 3
// speedup vs baseline: 2.2297x; 2.2297x over previous
#include <cuda_runtime.h>
#include <cuda_fp16.h>
#include <cstdint>

#define BATCH 4
#define H 128
#define W 128
#define HW (H*W)
#define CIN_X 256
#define CSKIP 128
#define CCAT 384
#define NPAIR (CCAT/2)       // 192 half2 channel-pairs
#define COUT 128
#define NPIX (BATCH*HW)
#define EPSV 1e-5f

// ---------------- scratch (device globals) -----------------------------------
__device__ __half2 g_cat_h2[(size_t)BATCH*NPAIR*HW];  // concat, fp16, pair-packed
__device__ __half2 g_wp[9*NPAIR*COUT];                // conv1 w [tap][ci_pair][oc]
__device__ float g_h[BATCH*COUT*HW];
__device__ float g_off[BATCH*18*HW];
__device__ float g_y[BATCH*COUT*HW];
__device__ float g_sum1[COUT], g_sq1[COUT], g_sum2[COUT], g_sq2[COUT];
__device__ float g_scale1[COUT], g_shift1[COUT], g_scale2[COUT], g_shift2[COUT];

// ---------------- kernel Z: zero stats ----------------------------------------
__global__ void k_zero() {
    int t = threadIdx.x;
    if (t < COUT) { g_sum1[t]=0.f; g_sq1[t]=0.f; g_sum2[t]=0.f; g_sq2[t]=0.f; }
}

// ---------------- kernel Wp: pack conv1 weights fp16 [tap][pair][oc] -----------
__global__ void k_wprep(const float* __restrict__ w) {
    int idx = blockIdx.x * 256 + threadIdx.x;
    if (idx >= 9*NPAIR*COUT) return;
    int oc = idx % COUT;
    int p  = (idx / COUT) % NPAIR;
    int tap = idx / (COUT*NPAIR);
    float w0 = w[((size_t)oc*CCAT + 2*p    )*9 + tap];
    float w1 = w[((size_t)oc*CCAT + 2*p + 1)*9 + tap];
    g_wp[idx] = __floats2half2_rn(w0, w1);
}

// ---------------- kernel A: upsample + concat -> fp16 pair-packed --------------
__global__ void k_upcat(const float* __restrict__ x, const float* __restrict__ skip) {
    int idx = blockIdx.x * blockDim.x + threadIdx.x;
    if (idx >= BATCH*NPAIR*HW) return;
    int xc = idx % W;
    int y  = (idx / W) % H;
    int p  = (idx / HW) % NPAIR;
    int b  = idx / (HW*NPAIR);
    float v0, v1;
    if (p < CSKIP/2) {
        v0 = skip[((size_t)(b*CSKIP + 2*p    )*H + y)*W + xc];
        v1 = skip[((size_t)(b*CSKIP + 2*p + 1)*H + y)*W + xc];
    } else {
        int ci0 = 2*p - CSKIP;
        float fy = (float)y  * (63.0f / 127.0f);
        float fx = (float)xc * (63.0f / 127.0f);
        int y0 = (int)fy, x0 = (int)fx;
        float wy = fy - (float)y0, wx = fx - (float)x0;
        int y1 = min(y0+1, 63), x1 = min(x0+1, 63);
        const float* xp0 = x + (size_t)(b*CIN_X + ci0)*(H/2)*(W/2);
        const float* xp1 = xp0 + (H/2)*(W/2);
        v0 = xp0[y0*64+x0]*(1.f-wy)*(1.f-wx) + xp0[y0*64+x1]*(1.f-wy)*wx
           + xp0[y1*64+x0]*wy*(1.f-wx)       + xp0[y1*64+x1]*wy*wx;
        v1 = xp1[y0*64+x0]*(1.f-wy)*(1.f-wx) + xp1[y0*64+x1]*(1.f-wy)*wx
           + xp1[y1*64+x0]*wy*(1.f-wx)       + xp1[y1*64+x1]*wy*wx;
    }
    g_cat_h2[idx] = __floats2half2_rn(v0, v1);
}

// ---------------- kernel B: conv1 via mma.sync fp16 implicit GEMM --------------
// block = 128 px (32x4) x 128 oc; 8 warps = 2(M) x 4(N); warp tile 64px x 32oc
#define ASTR 72   // halves per row (144B, 16B-aligned, 4-bank rotation)
__global__ __launch_bounds__(256) void k_conv1_mma() {
    __shared__ __half sA[128*ASTR];
    __shared__ __half sB[128*ASTR];
    int tid = threadIdx.x;
    int wid = tid >> 5, lane = tid & 31;
    int tileX = blockIdx.x * 32, tileY = blockIdx.y * 4;
    int b = blockIdx.z;
    int mBase = (wid & 1) * 64;
    int nBase = (wid >> 1) * 32;
    int grp = lane >> 2, tig = lane & 3;   // groupID, threadInGroup

    float acc[4][4][4];
    #pragma unroll
    for (int mi=0;mi<4;mi++)
        #pragma unroll
        for (int ni=0;ni<4;ni++)
            #pragma unroll
            for (int r=0;r<4;r++) acc[mi][ni][r]=0.f;

    int px_s = tid & 127;
    int half_s = tid >> 7;
    int ly_s = px_s >> 5, lx_s = px_s & 31;

    for (int tap = 0; tap < 9; tap++) {
        int ky = tap/3 - 1, kx = tap%3 - 1;
        int gy = tileY + ly_s + ky, gx = tileX + lx_s + kx;
        bool valid = (gy >= 0) && (gy < H) && (gx >= 0) && (gx < W);
        const __half2* catp = g_cat_h2 + (size_t)b*NPAIR*HW + (valid ? gy*W + gx : 0);
        const __half2* wtp  = g_wp + (size_t)tap*NPAIR*COUT;

        for (int c0 = 0; c0 < CCAT; c0 += 64) {
            int pbase = c0 >> 1;
            // stage A: 128 px x 32 pairs
            #pragma unroll
            for (int i = 0; i < 16; i++) {
                int pl = i*2 + half_s;
                uint32_t v = 0u;
                if (valid) v = *(const uint32_t*)&catp[(size_t)(pbase + pl)*HW];
                *(uint32_t*)&sA[px_s*ASTR + pl*2] = v;
            }
            // stage B: 128 oc x 32 pairs
            #pragma unroll
            for (int j = 0; j < 16; j++) {
                int idx = tid + j*256;
                int oc = idx & 127, pl = idx >> 7;
                *(uint32_t*)&sB[oc*ASTR + pl*2] =
                    *(const uint32_t*)&wtp[(size_t)(pbase + pl)*COUT + oc];
            }
            __syncthreads();
            #pragma unroll
            for (int ks = 0; ks < 4; ks++) {
                int k0 = ks*16;
                uint32_t af[4][4];
                #pragma unroll
                for (int mi = 0; mi < 4; mi++) {
                    int row = mBase + mi*16 + grp;
                    af[mi][0] = *(uint32_t*)&sA[ row     *ASTR + k0 + tig*2];
                    af[mi][1] = *(uint32_t*)&sA[(row + 8)*ASTR + k0 + tig*2];
                    af[mi][2] = *(uint32_t*)&sA[ row     *ASTR + k0 + 8 + tig*2];
                    af[mi][3] = *(uint32_t*)&sA[(row + 8)*ASTR + k0 + 8 + tig*2];
                }
                uint32_t bf[4][2];
                #pragma unroll
                for (int ni = 0; ni < 4; ni++) {
                    int nn = nBase + ni*8 + grp;
                    bf[ni][0] = *(uint32_t*)&sB[nn*ASTR + k0 + tig*2];
                    bf[ni][1] = *(uint32_t*)&sB[nn*ASTR + k0 + 8 + tig*2];
                }
                #pragma unroll
                for (int mi = 0; mi < 4; mi++)
                    #pragma unroll
                    for (int ni = 0; ni < 4; ni++) {
                        asm volatile(
                            "mma.sync.aligned.m16n8k16.row.col.f32.f16.f16.f32 "
                            "{%0,%1,%2,%3}, {%4,%5,%6,%7}, {%8,%9}, {%0,%1,%2,%3};"
                            : "+f"(acc[mi][ni][0]), "+f"(acc[mi][ni][1]),
                              "+f"(acc[mi][ni][2]), "+f"(acc[mi][ni][3])
                            : "r"(af[mi][0]), "r"(af[mi][1]), "r"(af[mi][2]), "r"(af[mi][3]),
                              "r"(bf[ni][0]), "r"(bf[ni][1]));
                    }
            }
            __syncthreads();
        }
    }

    // epilogue: c0,c1 -> row grp, cols tig*2+{0,1}; c2,c3 -> row grp+8
    #pragma unroll
    for (int mi = 0; mi < 4; mi++) {
        int px0 = mBase + mi*16 + grp;
        int px1 = px0 + 8;
        int y0 = tileY + (px0 >> 5), x0 = tileX + (px0 & 31);
        int y1 = tileY + (px1 >> 5), x1 = tileX + (px1 & 31);
        #pragma unroll
        for (int ni = 0; ni < 4; ni++) {
            int oc = nBase + ni*8 + tig*2;
            size_t b0 = ((size_t)(b*COUT + oc)*H);
            size_t b1 = ((size_t)(b*COUT + oc + 1)*H);
            g_h[(b0 + y0)*W + x0] = acc[mi][ni][0];
            g_h[(b1 + y0)*W + x0] = acc[mi][ni][1];
            g_h[(b0 + y1)*W + x1] = acc[mi][ni][2];
            g_h[(b1 + y1)*W + x1] = acc[mi][ni][3];
        }
    }
}

// ---------------- kernel S: per-channel sum/sumsq over g_h ---------------------
__global__ void k_stats1() {
    __shared__ float ss[256], sq[256];
    int c = blockIdx.x, b = blockIdx.y;
    int tid = threadIdx.x;
    const float* p = g_h + (size_t)(b*COUT + c)*HW;
    float s = 0.f, q = 0.f;
    for (int i = tid; i < HW; i += 256) { float v = p[i]; s += v; q += v*v; }
    ss[tid] = s; sq[tid] = q;
    __syncthreads();
    for (int st = 128; st > 0; st >>= 1) {
        if (tid < st) { ss[tid] += ss[tid+st]; sq[tid] += sq[tid+st]; }
        __syncthreads();
    }
    if (tid == 0) { atomicAdd(&g_sum1[c], ss[0]); atomicAdd(&g_sq1[c], sq[0]); }
}

// ---------------- kernel C: finalize BN scale/shift ----------------------------
__global__ void k_bnfin(int which, const float* __restrict__ g, const float* __restrict__ bb) {
    int c = threadIdx.x;
    if (c >= COUT) return;
    float s = which ? g_sum2[c] : g_sum1[c];
    float q = which ? g_sq2[c]  : g_sq1[c];
    float m = s / (float)NPIX;
    float v = q / (float)NPIX - m*m;
    float sc = g[c] * rsqrtf(v + EPSV);
    float sh = bb[c] - m * sc;
    if (which) { g_scale2[c] = sc; g_shift2[c] = sh; }
    else       { g_scale1[c] = sc; g_shift1[c] = sh; }
}

// ---------------- kernel D: BN1 + ReLU in place on g_h -------------------------
__global__ void k_bnrelu1() {
    int idx = blockIdx.x * 256 + threadIdx.x;
    if (idx >= BATCH*COUT*HW) return;
    int c = (idx / HW) % COUT;
    float v = g_h[idx] * g_scale1[c] + g_shift1[c];
    g_h[idx] = fmaxf(v, 0.f);
}

// ---------------- kernel E: offset conv 3x3 (128->18) + bias -------------------
__global__ __launch_bounds__(256) void k_offconv(const float* __restrict__ w,
                                                 const float* __restrict__ bias) {
    __shared__ float sIn[8][18][34];
    __shared__ float sW[8][9][18];
    int tid = threadIdx.x;
    int tx = tid & 31, tyq = tid >> 5;
    int tileX = blockIdx.x * 32, tileY = blockIdx.y * 16;
    int b = blockIdx.z;
    float acc0[18], acc1[18];
    #pragma unroll
    for (int i=0;i<18;i++){ acc0[i]=0.f; acc1[i]=0.f; }

    for (int c0 = 0; c0 < COUT; c0 += 8) {
        for (int i = tid; i < 8*18*34; i += 256) {
            int ci = i / 612, r = i % 612, ly = r / 34, lx = r % 34;
            int gy = tileY + ly - 1, gx = tileX + lx - 1;
            float v = 0.f;
            if (gy >= 0 && gy < H && gx >= 0 && gx < W)
                v = g_h[((size_t)(b*COUT + c0 + ci)*H + gy)*W + gx];
            sIn[ci][ly][lx] = v;
        }
        for (int i = tid; i < 8*9*18; i += 256) {
            int ci = i / 162, r = i % 162, tap = r / 18, oc = r % 18;
            sW[ci][tap][oc] = w[((size_t)oc*COUT + c0 + ci)*9 + tap];
        }
        __syncthreads();
        #pragma unroll
        for (int ci = 0; ci < 8; ci++) {
            #pragma unroll
            for (int ky = 0; ky < 3; ky++) {
                #pragma unroll
                for (int kx = 0; kx < 3; kx++) {
                    float v0 = sIn[ci][tyq + ky][tx + kx];
                    float v1 = sIn[ci][tyq + 8 + ky][tx + kx];
                    #pragma unroll
                    for (int oc = 0; oc < 18; oc++) {
                        float wv = sW[ci][ky*3+kx][oc];
                        acc0[oc] += v0 * wv;
                        acc1[oc] += v1 * wv;
                    }
                }
            }
        }
        __syncthreads();
    }
    int y0 = tileY + tyq, y1 = y0 + 8, xg = tileX + tx;
    #pragma unroll
    for (int oc = 0; oc < 18; oc++) {
        float bv = bias[oc];
        g_off[((size_t)(b*18 + oc)*H + y0)*W + xg] = acc0[oc] + bv;
        g_off[((size_t)(b*18 + oc)*H + y1)*W + xg] = acc1[oc] + bv;
    }
}

// ---------------- kernel F: deformable conv + BN2 stats ------------------------
__global__ __launch_bounds__(256) void k_deform(const float* __restrict__ dw,
                                                const float* __restrict__ db) {
    __shared__ float sGeo[4][128];
    __shared__ float sS[8][128];
    __shared__ float sWk[64][8];
    __shared__ float sSum[64], sSq[64];
    int tid = threadIdx.x;
    int pxg = tid & 31, ocg = tid >> 5;
    int tileX = blockIdx.x * 32, tileY = blockIdx.y * 4;
    int b = blockIdx.z >> 1;
    int ocBase = (blockIdx.z & 1) * 64;

    float acc[4][8];
    #pragma unroll
    for (int p=0;p<4;p++)
        #pragma unroll
        for (int j=0;j<8;j++) acc[p][j]=0.f;

    for (int k = 0; k < 9; k++) {
        if (tid < 128) {
            int ly = tid >> 5, lx = tid & 31;
            int y = tileY + ly, x = tileX + lx;
            float dy = g_off[((size_t)(b*18 + 2*k    )*H + y)*W + x];
            float dx = g_off[((size_t)(b*18 + 2*k + 1)*H + y)*W + x];
            float py = (float)y + (float)(k/3 - 1) + dy;
            float px = (float)x + (float)(k%3 - 1) + dx;
            float y0 = floorf(py), x0 = floorf(px);
            sGeo[0][tid] = y0;
            sGeo[1][tid] = x0;
            sGeo[2][tid] = py - y0;
            sGeo[3][tid] = px - x0;
        }
        __syncthreads();
        for (int c0 = 0; c0 < COUT; c0 += 8) {
            #pragma unroll
            for (int i = 0; i < 4; i++) {
                int idx = tid + i*256;
                int ci = idx >> 7, p = idx & 127;
                float y0 = sGeo[0][p], x0 = sGeo[1][p];
                float wy = sGeo[2][p], wx = sGeo[3][p];
                int yi = (int)y0, xi = (int)x0;
                const float* hp = g_h + (size_t)(b*COUT + c0 + ci)*HW;
                float v00=0.f, v01=0.f, v10=0.f, v11=0.f;
                bool yv0 = (yi   >= 0) && (yi   < H);
                bool yv1 = (yi+1 >= 0) && (yi+1 < H);
                bool xv0 = (xi   >= 0) && (xi   < W);
                bool xv1 = (xi+1 >= 0) && (xi+1 < W);
                if (yv0 && xv0) v00 = hp[yi*W + xi];
                if (yv0 && xv1) v01 = hp[yi*W + xi + 1];
                if (yv1 && xv0) v10 = hp[(yi+1)*W + xi];
                if (yv1 && xv1) v11 = hp[(yi+1)*W + xi + 1];
                sS[ci][p] = v00*(1.f-wy)*(1.f-wx) + v01*(1.f-wy)*wx
                          + v10*wy*(1.f-wx)       + v11*wy*wx;
            }
            #pragma unroll
            for (int i = 0; i < 2; i++) {
                int idx = tid + i*256;
                int oc = idx >> 3, ci = idx & 7;
                sWk[oc][ci] = dw[((size_t)(ocBase + oc)*COUT + c0 + ci)*9 + k];
            }
            __syncthreads();
            #pragma unroll
            for (int ci = 0; ci < 8; ci++) {
                float v[4];
                #pragma unroll
                for (int p = 0; p < 4; p++) v[p] = sS[ci][p*32 + pxg];
                #pragma unroll
                for (int j = 0; j < 8; j++) {
                    float wv = sWk[ocg*8 + j][ci];
                    #pragma unroll
                    for (int p = 0; p < 4; p++) acc[p][j] += v[p] * wv;
                }
            }
            __syncthreads();
        }
    }

    if (tid < 64) { sSum[tid] = 0.f; sSq[tid] = 0.f; }
    __syncthreads();
    int x = tileX + pxg;
    #pragma unroll
    for (int j = 0; j < 8; j++) {
        int ocl = ocg*8 + j;
        int oc = ocBase + ocl;
        float bias = db[oc];
        float ls = 0.f, lq = 0.f;
        #pragma unroll
        for (int p = 0; p < 4; p++) {
            int y = tileY + p;
            float v = acc[p][j] + bias;
            g_y[((size_t)(b*COUT + oc)*H + y)*W + x] = v;
            ls += v; lq += v*v;
        }
        atomicAdd(&sSum[ocl], ls);
        atomicAdd(&sSq[ocl], lq);
    }
    __syncthreads();
    if (tid < 64) {
        atomicAdd(&g_sum2[ocBase + tid], sSum[tid]);
        atomicAdd(&g_sq2[ocBase + tid], sSq[tid]);
    }
}

// ---------------- kernel H: BN2 + ReLU -> d_out --------------------------------
__global__ void k_bnrelu2(float* __restrict__ out) {
    int idx = blockIdx.x * 256 + threadIdx.x;
    if (idx >= BATCH*COUT*HW) return;
    int c = (idx / HW) % COUT;
    float v = g_y[idx] * g_scale2[c] + g_shift2[c];
    out[idx] = fmaxf(v, 0.f);
}

// ---------------- launch --------------------------------------------------------
extern "C" void kernel_launch(void* const* d_in, const int* in_sizes, int n_in,
                              void* d_out, int out_size) {
    const float* x       = (const float*)d_in[0];
    const float* skip    = (const float*)d_in[1];
    const float* conv1_w = (const float*)d_in[2];
    const float* bn1_g   = (const float*)d_in[3];
    const float* bn1_b   = (const float*)d_in[4];
    const float* off_w   = (const float*)d_in[5];
    const float* off_b   = (const float*)d_in[6];
    const float* def_w   = (const float*)d_in[7];
    const float* def_b   = (const float*)d_in[8];
    const float* bn2_g   = (const float*)d_in[9];
    const float* bn2_b   = (const float*)d_in[10];
    float* out = (float*)d_out;

    k_zero<<<1, 256>>>();
    k_wprep<<<(9*NPAIR*COUT + 255)/256, 256>>>(conv1_w);

    int ncat = BATCH*NPAIR*HW;
    k_upcat<<<(ncat + 255)/256, 256>>>(x, skip);

    k_conv1_mma<<<dim3(W/32, H/4, BATCH), 256>>>();
    k_stats1<<<dim3(COUT, BATCH), 256>>>();
    k_bnfin<<<1, COUT>>>(0, bn1_g, bn1_b);

    int nh = BATCH*COUT*HW;
    k_bnrelu1<<<(nh + 255)/256, 256>>>();

    k_offconv<<<dim3(W/32, H/16, BATCH), 256>>>(off_w, off_b);

    k_deform<<<dim3(W/32, H/4, BATCH*2), 256>>>(def_w, def_b);
    k_bnfin<<<1, COUT>>>(1, bn2_g, bn2_b);

    k_bnrelu2<<<(nh + 255)/256, 256>>>(out);
}

// round 4
// speedup vs baseline: 4.5359x; 2.0343x over previous
#include <cuda_runtime.h>
#include <cuda_fp16.h>
#include <cstdint>

#define BATCH 4
#define H 128
#define W 128
#define HW (H*W)
#define CIN_X 256
#define CSKIP 128
#define CCAT 384
#define NPAIR (CCAT/2)
#define COUT 128
#define NPIX (BATCH*HW)
#define EPSV 1e-5f
#define ASTR 72   // halves per smem row (144B): 4-bank rotation, ldmatrix conflict-free

// ---------------- scratch ------------------------------------------------------
__device__ __half2 g_cat_h2[(size_t)BATCH*NPAIR*HW];  // concat fp16, pair-packed planar
__device__ __half2 g_wp[9*NPAIR*COUT];                // conv1 w [tap][ci_pair][oc]
__device__ __half2 g_wp2[9*(COUT/2)*COUT];            // def  w [tap][ci_pair][oc]
__device__ float   g_h[(size_t)BATCH*HW*COUT];        // conv1 out, CHANNELS-LAST fp32
__device__ __half2 g_hh[(size_t)BATCH*HW*(COUT/2)];   // BN1+ReLU h, CHANNELS-LAST fp16
__device__ float   g_off[BATCH*18*HW];                // offsets (planar)
__device__ float   g_y[(size_t)BATCH*HW*COUT];        // deform out, CHANNELS-LAST fp32
__device__ float g_sum1[COUT], g_sq1[COUT], g_sum2[COUT], g_sq2[COUT];
__device__ float g_scale1[COUT], g_shift1[COUT], g_scale2[COUT], g_shift2[COUT];

// ---------------- helpers ------------------------------------------------------
__device__ __forceinline__ void ldm_x4(uint32_t& r0, uint32_t& r1, uint32_t& r2,
                                       uint32_t& r3, uint32_t addr) {
    asm volatile("ldmatrix.sync.aligned.m8n8.x4.shared.b16 {%0,%1,%2,%3}, [%4];"
                 : "=r"(r0), "=r"(r1), "=r"(r2), "=r"(r3) : "r"(addr));
}
__device__ __forceinline__ void mma16816(float* c, const uint32_t* a, const uint32_t* b) {
    asm volatile(
        "mma.sync.aligned.m16n8k16.row.col.f32.f16.f16.f32 "
        "{%0,%1,%2,%3}, {%4,%5,%6,%7}, {%8,%9}, {%0,%1,%2,%3};"
        : "+f"(c[0]), "+f"(c[1]), "+f"(c[2]), "+f"(c[3])
        : "r"(a[0]), "r"(a[1]), "r"(a[2]), "r"(a[3]), "r"(b[0]), "r"(b[1]));
}

// ---------------- kernel Z -----------------------------------------------------
__global__ void k_zero() {
    int t = threadIdx.x;
    if (t < COUT) { g_sum1[t]=0.f; g_sq1[t]=0.f; g_sum2[t]=0.f; g_sq2[t]=0.f; }
}

// ---------------- weight packs -------------------------------------------------
__global__ void k_wprep(const float* __restrict__ w) {
    int idx = blockIdx.x * 256 + threadIdx.x;
    if (idx >= 9*NPAIR*COUT) return;
    int oc = idx % COUT;
    int p  = (idx / COUT) % NPAIR;
    int tap = idx / (COUT*NPAIR);
    float w0 = w[((size_t)oc*CCAT + 2*p    )*9 + tap];
    float w1 = w[((size_t)oc*CCAT + 2*p + 1)*9 + tap];
    g_wp[idx] = __floats2half2_rn(w0, w1);
}
__global__ void k_wprep2(const float* __restrict__ w) {
    int idx = blockIdx.x * 256 + threadIdx.x;
    if (idx >= 9*(COUT/2)*COUT) return;
    int oc = idx % COUT;
    int p  = (idx / COUT) % (COUT/2);
    int tap = idx / (COUT*(COUT/2));
    float w0 = w[((size_t)oc*COUT + 2*p    )*9 + tap];
    float w1 = w[((size_t)oc*COUT + 2*p + 1)*9 + tap];
    g_wp2[idx] = __floats2half2_rn(w0, w1);
}

// ---------------- kernel A: upsample + concat -> fp16 pair-packed planar --------
__global__ void k_upcat(const float* __restrict__ x, const float* __restrict__ skip) {
    int idx = blockIdx.x * blockDim.x + threadIdx.x;
    if (idx >= BATCH*NPAIR*HW) return;
    int xc = idx % W;
    int y  = (idx / W) % H;
    int p  = (idx / HW) % NPAIR;
    int b  = idx / (HW*NPAIR);
    float v0, v1;
    if (p < CSKIP/2) {
        v0 = skip[((size_t)(b*CSKIP + 2*p    )*H + y)*W + xc];
        v1 = skip[((size_t)(b*CSKIP + 2*p + 1)*H + y)*W + xc];
    } else {
        int ci0 = 2*p - CSKIP;
        float fy = (float)y  * (63.0f / 127.0f);
        float fx = (float)xc * (63.0f / 127.0f);
        int y0 = (int)fy, x0 = (int)fx;
        float wy = fy - (float)y0, wx = fx - (float)x0;
        int y1 = min(y0+1, 63), x1 = min(x0+1, 63);
        const float* xp0 = x + (size_t)(b*CIN_X + ci0)*(H/2)*(W/2);
        const float* xp1 = xp0 + (H/2)*(W/2);
        v0 = xp0[y0*64+x0]*(1.f-wy)*(1.f-wx) + xp0[y0*64+x1]*(1.f-wy)*wx
           + xp0[y1*64+x0]*wy*(1.f-wx)       + xp0[y1*64+x1]*wy*wx;
        v1 = xp1[y0*64+x0]*(1.f-wy)*(1.f-wx) + xp1[y0*64+x1]*(1.f-wy)*wx
           + xp1[y1*64+x0]*wy*(1.f-wx)       + xp1[y1*64+x1]*wy*wx;
    }
    g_cat_h2[idx] = __floats2half2_rn(v0, v1);
}

// ---------------- kernel B: conv1 mma + ldmatrix + fused BN1 stats --------------
__global__ __launch_bounds__(256) void k_conv1_mma() {
    __shared__ __half sA[128*ASTR];
    __shared__ __half sB[128*ASTR];
    __shared__ float sS[COUT], sQ[COUT];
    int tid = threadIdx.x;
    int wid = tid >> 5, lane = tid & 31;
    int tileX = blockIdx.x * 32, tileY = blockIdx.y * 4;
    int b = blockIdx.z;
    int mBase = (wid & 1) * 64;
    int nBase = (wid >> 1) * 32;
    int grp = lane >> 2, tig = lane & 3;

    uint32_t sA_u = (uint32_t)__cvta_generic_to_shared(sA);
    uint32_t sB_u = (uint32_t)__cvta_generic_to_shared(sB);
    uint32_t aAddr = sA_u + (uint32_t)(((mBase + (lane & 15))*ASTR + (lane >> 4)*8) * 2);
    uint32_t bAddr = sB_u + (uint32_t)(((nBase + (lane & 7) + ((lane >> 4) & 1)*8)*ASTR
                                        + ((lane >> 3) & 1)*8) * 2);

    float acc[4][4][4];
    #pragma unroll
    for (int mi=0;mi<4;mi++)
        #pragma unroll
        for (int ni=0;ni<4;ni++)
            #pragma unroll
            for (int r=0;r<4;r++) acc[mi][ni][r]=0.f;

    int px_s = tid & 127;
    int half_s = tid >> 7;
    int ly_s = px_s >> 5, lx_s = px_s & 31;

    for (int tap = 0; tap < 9; tap++) {
        int ky = tap/3 - 1, kx = tap%3 - 1;
        int gy = tileY + ly_s + ky, gx = tileX + lx_s + kx;
        bool valid = (gy >= 0) && (gy < H) && (gx >= 0) && (gx < W);
        const __half2* catp = g_cat_h2 + (size_t)b*NPAIR*HW + (valid ? gy*W + gx : 0);
        const __half2* wtp  = g_wp + (size_t)tap*NPAIR*COUT;

        for (int c0 = 0; c0 < CCAT; c0 += 64) {
            int pbase = c0 >> 1;
            #pragma unroll
            for (int i = 0; i < 16; i++) {
                int pl = i*2 + half_s;
                uint32_t v = 0u;
                if (valid) v = *(const uint32_t*)&catp[(size_t)(pbase + pl)*HW];
                *(uint32_t*)&sA[px_s*ASTR + pl*2] = v;
            }
            #pragma unroll
            for (int j = 0; j < 16; j++) {
                int idx = tid + j*256;
                int oc = idx & 127, pl = idx >> 7;
                *(uint32_t*)&sB[oc*ASTR + pl*2] =
                    *(const uint32_t*)&wtp[(size_t)(pbase + pl)*COUT + oc];
            }
            __syncthreads();
            #pragma unroll
            for (int ks = 0; ks < 4; ks++) {
                uint32_t af[4][4], bf[4][2];
                #pragma unroll
                for (int mi = 0; mi < 4; mi++)
                    ldm_x4(af[mi][0], af[mi][1], af[mi][2], af[mi][3],
                           aAddr + mi*(16*ASTR*2) + ks*32);
                ldm_x4(bf[0][0], bf[0][1], bf[1][0], bf[1][1], bAddr + ks*32);
                ldm_x4(bf[2][0], bf[2][1], bf[3][0], bf[3][1],
                       bAddr + 16*ASTR*2 + ks*32);
                #pragma unroll
                for (int mi = 0; mi < 4; mi++)
                    #pragma unroll
                    for (int ni = 0; ni < 4; ni++)
                        mma16816(acc[mi][ni], af[mi], bf[ni]);
            }
            __syncthreads();
        }
    }

    if (tid < COUT) { sS[tid] = 0.f; sQ[tid] = 0.f; }
    __syncthreads();
    #pragma unroll
    for (int ni = 0; ni < 4; ni++) {
        int oc = nBase + ni*8 + tig*2;
        float s0=0.f,q0=0.f,s1=0.f,q1=0.f;
        #pragma unroll
        for (int mi = 0; mi < 4; mi++) {
            int px0 = mBase + mi*16 + grp;
            int px1 = px0 + 8;
            size_t gp0 = ((size_t)b*HW + (tileY + (px0>>5))*W + tileX + (px0&31))*COUT;
            size_t gp1 = ((size_t)b*HW + (tileY + (px1>>5))*W + tileX + (px1&31))*COUT;
            float a0 = acc[mi][ni][0], a1 = acc[mi][ni][1];
            float a2 = acc[mi][ni][2], a3 = acc[mi][ni][3];
            *(float2*)&g_h[gp0 + oc] = make_float2(a0, a1);
            *(float2*)&g_h[gp1 + oc] = make_float2(a2, a3);
            s0 += a0 + a2; q0 += a0*a0 + a2*a2;
            s1 += a1 + a3; q1 += a1*a1 + a3*a3;
        }
        atomicAdd(&sS[oc], s0);   atomicAdd(&sQ[oc], q0);
        atomicAdd(&sS[oc+1], s1); atomicAdd(&sQ[oc+1], q1);
    }
    __syncthreads();
    if (tid < COUT) {
        atomicAdd(&g_sum1[tid], sS[tid]);
        atomicAdd(&g_sq1[tid], sQ[tid]);
    }
}

// ---------------- kernel C: finalize BN ------------------------------------------
__global__ void k_bnfin(int which, const float* __restrict__ g, const float* __restrict__ bb) {
    int c = threadIdx.x;
    if (c >= COUT) return;
    float s = which ? g_sum2[c] : g_sum1[c];
    float q = which ? g_sq2[c]  : g_sq1[c];
    float m = s / (float)NPIX;
    float v = q / (float)NPIX - m*m;
    float sc = g[c] * rsqrtf(v + EPSV);
    float sh = bb[c] - m * sc;
    if (which) { g_scale2[c] = sc; g_shift2[c] = sh; }
    else       { g_scale1[c] = sc; g_shift1[c] = sh; }
}

// ---------------- kernel D: BN1+ReLU, ch-last fp32 -> ch-last fp16 ----------------
__global__ void k_bnrelu1() {
    int idx = blockIdx.x * 256 + threadIdx.x;
    if (idx >= BATCH*HW*(COUT/2)) return;
    int p = idx & 63;
    float2 v = *(const float2*)&g_h[(size_t)idx*2];
    float r0 = fmaxf(v.x * g_scale1[2*p]   + g_shift1[2*p],   0.f);
    float r1 = fmaxf(v.y * g_scale1[2*p+1] + g_shift1[2*p+1], 0.f);
    g_hh[idx] = __floats2half2_rn(r0, r1);
}

// ---------------- kernel E: offset conv (reads ch-last fp16 h) --------------------
__global__ __launch_bounds__(256) void k_offconv(const float* __restrict__ w,
                                                 const float* __restrict__ bias) {
    __shared__ float sIn[8][18][34];
    __shared__ float sW[8][9][18];
    int tid = threadIdx.x;
    int tx = tid & 31, tyq = tid >> 5;
    int tileX = blockIdx.x * 32, tileY = blockIdx.y * 16;
    int b = blockIdx.z;
    float acc0[18], acc1[18];
    #pragma unroll
    for (int i=0;i<18;i++){ acc0[i]=0.f; acc1[i]=0.f; }

    for (int c0 = 0; c0 < COUT; c0 += 8) {
        for (int i = tid; i < 18*34; i += 256) {
            int ly = i / 34, lx = i % 34;
            int gy = tileY + ly - 1, gx = tileX + lx - 1;
            float v[8] = {0,0,0,0,0,0,0,0};
            if (gy >= 0 && gy < H && gx >= 0 && gx < W) {
                const uint4* p = (const uint4*)(g_hh + ((size_t)b*HW + gy*W + gx)*64 + (c0>>1));
                uint4 q = *p;
                __half2 h0 = *(__half2*)&q.x, h1 = *(__half2*)&q.y;
                __half2 h2 = *(__half2*)&q.z, h3 = *(__half2*)&q.w;
                float2 f0 = __half22float2(h0), f1 = __half22float2(h1);
                float2 f2 = __half22float2(h2), f3 = __half22float2(h3);
                v[0]=f0.x; v[1]=f0.y; v[2]=f1.x; v[3]=f1.y;
                v[4]=f2.x; v[5]=f2.y; v[6]=f3.x; v[7]=f3.y;
            }
            #pragma unroll
            for (int ci = 0; ci < 8; ci++) sIn[ci][ly][lx] = v[ci];
        }
        for (int i = tid; i < 8*9*18; i += 256) {
            int ci = i / 162, r = i % 162, tap = r / 18, oc = r % 18;
            sW[ci][tap][oc] = w[((size_t)oc*COUT + c0 + ci)*9 + tap];
        }
        __syncthreads();
        #pragma unroll
        for (int ci = 0; ci < 8; ci++) {
            #pragma unroll
            for (int ky = 0; ky < 3; ky++) {
                #pragma unroll
                for (int kx = 0; kx < 3; kx++) {
                    float v0 = sIn[ci][tyq + ky][tx + kx];
                    float v1 = sIn[ci][tyq + 8 + ky][tx + kx];
                    #pragma unroll
                    for (int oc = 0; oc < 18; oc++) {
                        float wv = sW[ci][ky*3+kx][oc];
                        acc0[oc] += v0 * wv;
                        acc1[oc] += v1 * wv;
                    }
                }
            }
        }
        __syncthreads();
    }
    int y0 = tileY + tyq, y1 = y0 + 8, xg = tileX + tx;
    #pragma unroll
    for (int oc = 0; oc < 18; oc++) {
        float bv = bias[oc];
        g_off[((size_t)(b*18 + oc)*H + y0)*W + xg] = acc0[oc] + bv;
        g_off[((size_t)(b*18 + oc)*H + y1)*W + xg] = acc1[oc] + bv;
    }
}

// ---------------- kernel F: deformable conv via mma + fused BN2 stats -------------
__global__ __launch_bounds__(256) void k_deform_mma(const float* __restrict__ db) {
    __shared__ __half sA[128*ASTR];
    __shared__ __half sB[128*ASTR];
    __shared__ int   sOff[4][128];
    __shared__ float sWgt[4][128];
    __shared__ float sS[COUT], sQ[COUT];
    int tid = threadIdx.x;
    int wid = tid >> 5, lane = tid & 31;
    int tileX = blockIdx.x * 32, tileY = blockIdx.y * 4;
    int b = blockIdx.z;
    int mBase = (wid & 1) * 64;
    int nBase = (wid >> 1) * 32;
    int grp = lane >> 2, tig = lane & 3;

    uint32_t sA_u = (uint32_t)__cvta_generic_to_shared(sA);
    uint32_t sB_u = (uint32_t)__cvta_generic_to_shared(sB);
    uint32_t aAddr = sA_u + (uint32_t)(((mBase + (lane & 15))*ASTR + (lane >> 4)*8) * 2);
    uint32_t bAddr = sB_u + (uint32_t)(((nBase + (lane & 7) + ((lane >> 4) & 1)*8)*ASTR
                                        + ((lane >> 3) & 1)*8) * 2);

    float acc[4][4][4];
    #pragma unroll
    for (int mi=0;mi<4;mi++)
        #pragma unroll
        for (int ni=0;ni<4;ni++)
            #pragma unroll
            for (int r=0;r<4;r++) acc[mi][ni][r]=0.f;

    int px_s = tid & 127;
    int half_s = tid >> 7;

    for (int tap = 0; tap < 9; tap++) {
        if (tid < 128) {
            int ly = tid >> 5, lx = tid & 31;
            int y = tileY + ly, x = tileX + lx;
            float dy = g_off[((size_t)(b*18 + 2*tap    )*H + y)*W + x];
            float dx = g_off[((size_t)(b*18 + 2*tap + 1)*H + y)*W + x];
            float py = (float)y + (float)(tap/3 - 1) + dy;
            float pxx = (float)x + (float)(tap%3 - 1) + dx;
            float y0f = floorf(py), x0f = floorf(pxx);
            float wy = py - y0f, wx = pxx - x0f;
            int yi = (int)y0f, xi = (int)x0f;
            bool yv0 = (yi >= 0) && (yi < H);
            bool yv1 = (yi+1 >= 0) && (yi+1 < H);
            bool xv0 = (xi >= 0) && (xi < W);
            bool xv1 = (xi+1 >= 0) && (xi+1 < W);
            int yc0 = min(max(yi, 0), H-1), yc1 = min(max(yi+1, 0), H-1);
            int xc0 = min(max(xi, 0), W-1), xc1 = min(max(xi+1, 0), W-1);
            int base = b*HW;
            sOff[0][tid] = (base + yc0*W + xc0) << 6;
            sOff[1][tid] = (base + yc0*W + xc1) << 6;
            sOff[2][tid] = (base + yc1*W + xc0) << 6;
            sOff[3][tid] = (base + yc1*W + xc1) << 6;
            sWgt[0][tid] = (yv0 && xv0) ? (1.f-wy)*(1.f-wx) : 0.f;
            sWgt[1][tid] = (yv0 && xv1) ? (1.f-wy)*wx       : 0.f;
            sWgt[2][tid] = (yv1 && xv0) ? wy*(1.f-wx)       : 0.f;
            sWgt[3][tid] = (yv1 && xv1) ? wy*wx             : 0.f;
        }
        __syncthreads();

        const __half2* wtp = g_wp2 + (size_t)tap*(COUT/2)*COUT;
        int o0 = sOff[0][px_s], o1 = sOff[1][px_s], o2 = sOff[2][px_s], o3 = sOff[3][px_s];
        float w0 = sWgt[0][px_s], w1 = sWgt[1][px_s], w2 = sWgt[2][px_s], w3 = sWgt[3][px_s];

        for (int c0 = 0; c0 < COUT; c0 += 64) {
            int pb = (c0 >> 1) + half_s*16;
            const uint4* p0 = (const uint4*)(g_hh + o0 + pb);
            const uint4* p1 = (const uint4*)(g_hh + o1 + pb);
            const uint4* p2 = (const uint4*)(g_hh + o2 + pb);
            const uint4* p3 = (const uint4*)(g_hh + o3 + pb);
            #pragma unroll
            for (int j = 0; j < 4; j++) {
                uint4 q0 = p0[j], q1 = p1[j], q2 = p2[j], q3 = p3[j];
                uint32_t res[4];
                const uint32_t* a0 = (const uint32_t*)&q0;
                const uint32_t* a1 = (const uint32_t*)&q1;
                const uint32_t* a2 = (const uint32_t*)&q2;
                const uint32_t* a3 = (const uint32_t*)&q3;
                #pragma unroll
                for (int e = 0; e < 4; e++) {
                    float2 f0 = __half22float2(*(__half2*)&a0[e]);
                    float2 f1 = __half22float2(*(__half2*)&a1[e]);
                    float2 f2 = __half22float2(*(__half2*)&a2[e]);
                    float2 f3 = __half22float2(*(__half2*)&a3[e]);
                    float rx = w0*f0.x + w1*f1.x + w2*f2.x + w3*f3.x;
                    float ry = w0*f0.y + w1*f1.y + w2*f2.y + w3*f3.y;
                    __half2 hv = __floats2half2_rn(rx, ry);
                    res[e] = *(uint32_t*)&hv;
                }
                *(uint4*)&sA[px_s*ASTR + (half_s*16 + j*4)*2] = *(uint4*)res;
            }
            #pragma unroll
            for (int j = 0; j < 16; j++) {
                int idx = tid + j*256;
                int oc = idx & 127, pl = idx >> 7;
                *(uint32_t*)&sB[oc*ASTR + pl*2] =
                    *(const uint32_t*)&wtp[(size_t)((c0>>1) + pl)*COUT + oc];
            }
            __syncthreads();
            #pragma unroll
            for (int ks = 0; ks < 4; ks++) {
                uint32_t af[4][4], bf[4][2];
                #pragma unroll
                for (int mi = 0; mi < 4; mi++)
                    ldm_x4(af[mi][0], af[mi][1], af[mi][2], af[mi][3],
                           aAddr + mi*(16*ASTR*2) + ks*32);
                ldm_x4(bf[0][0], bf[0][1], bf[1][0], bf[1][1], bAddr + ks*32);
                ldm_x4(bf[2][0], bf[2][1], bf[3][0], bf[3][1],
                       bAddr + 16*ASTR*2 + ks*32);
                #pragma unroll
                for (int mi = 0; mi < 4; mi++)
                    #pragma unroll
                    for (int ni = 0; ni < 4; ni++)
                        mma16816(acc[mi][ni], af[mi], bf[ni]);
            }
            __syncthreads();
        }
    }

    if (tid < COUT) { sS[tid] = 0.f; sQ[tid] = 0.f; }
    __syncthreads();
    #pragma unroll
    for (int ni = 0; ni < 4; ni++) {
        int oc = nBase + ni*8 + tig*2;
        float b0 = db[oc], b1 = db[oc+1];
        float s0=0.f,q0=0.f,s1=0.f,q1=0.f;
        #pragma unroll
        for (int mi = 0; mi < 4; mi++) {
            int px0 = mBase + mi*16 + grp;
            int px1 = px0 + 8;
            size_t gp0 = ((size_t)b*HW + (tileY + (px0>>5))*W + tileX + (px0&31))*COUT;
            size_t gp1 = ((size_t)b*HW + (tileY + (px1>>5))*W + tileX + (px1&31))*COUT;
            float a0 = acc[mi][ni][0] + b0, a1 = acc[mi][ni][1] + b1;
            float a2 = acc[mi][ni][2] + b0, a3 = acc[mi][ni][3] + b1;
            *(float2*)&g_y[gp0 + oc] = make_float2(a0, a1);
            *(float2*)&g_y[gp1 + oc] = make_float2(a2, a3);
            s0 += a0 + a2; q0 += a0*a0 + a2*a2;
            s1 += a1 + a3; q1 += a1*a1 + a3*a3;
        }
        atomicAdd(&sS[oc], s0);   atomicAdd(&sQ[oc], q0);
        atomicAdd(&sS[oc+1], s1); atomicAdd(&sQ[oc+1], q1);
    }
    __syncthreads();
    if (tid < COUT) {
        atomicAdd(&g_sum2[tid], sS[tid]);
        atomicAdd(&g_sq2[tid], sQ[tid]);
    }
}

// ---------------- kernel H: BN2+ReLU, ch-last -> planar out -----------------------
__global__ __launch_bounds__(256) void k_bnrelu2(float* __restrict__ out) {
    __shared__ float s[32][129];
    int tid = threadIdx.x;
    int px0 = blockIdx.x * 32;
    int b = blockIdx.y;
    #pragma unroll
    for (int j = 0; j < 16; j++) {
        int idx = tid + j*256;
        int pxl = idx >> 7, c = idx & 127;
        s[pxl][c] = g_y[((size_t)b*HW + px0 + pxl)*COUT + c];
    }
    __syncthreads();
    #pragma unroll
    for (int j = 0; j < 16; j++) {
        int idx = tid + j*256;
        int c = idx >> 5, pxl = idx & 31;
        float v = s[pxl][c] * g_scale2[c] + g_shift2[c];
        out[((size_t)(b*COUT + c)*HW) + px0 + pxl] = fmaxf(v, 0.f);
    }
}

// ---------------- launch -----------------------------------------------------------
extern "C" void kernel_launch(void* const* d_in, const int* in_sizes, int n_in,
                              void* d_out, int out_size) {
    const float* x       = (const float*)d_in[0];
    const float* skip    = (const float*)d_in[1];
    const float* conv1_w = (const float*)d_in[2];
    const float* bn1_g   = (const float*)d_in[3];
    const float* bn1_b   = (const float*)d_in[4];
    const float* off_w   = (const float*)d_in[5];
    const float* off_b   = (const float*)d_in[6];
    const float* def_w   = (const float*)d_in[7];
    const float* def_b   = (const float*)d_in[8];
    const float* bn2_g   = (const float*)d_in[9];
    const float* bn2_b   = (const float*)d_in[10];
    float* out = (float*)d_out;

    k_zero<<<1, 256>>>();
    k_wprep<<<(9*NPAIR*COUT + 255)/256, 256>>>(conv1_w);
    k_wprep2<<<(9*(COUT/2)*COUT + 255)/256, 256>>>(def_w);

    int ncat = BATCH*NPAIR*HW;
    k_upcat<<<(ncat + 255)/256, 256>>>(x, skip);

    k_conv1_mma<<<dim3(W/32, H/4, BATCH), 256>>>();
    k_bnfin<<<1, COUT>>>(0, bn1_g, bn1_b);

    int nhp = BATCH*HW*(COUT/2);
    k_bnrelu1<<<(nhp + 255)/256, 256>>>();

    k_offconv<<<dim3(W/32, H/16, BATCH), 256>>>(off_w, off_b);

    k_deform_mma<<<dim3(W/32, H/4, BATCH), 256>>>(def_b);
    k_bnfin<<<1, COUT>>>(1, bn2_g, bn2_b);

    k_bnrelu2<<<dim3(HW/32, BATCH), 256>>>(out);
}

// round 5
// speedup vs baseline: 5.2208x; 1.1510x over previous
#include <cuda_runtime.h>
#include <cuda_fp16.h>
#include <cstdint>

#define BATCH 4
#define H 128
#define W 128
#define HW (H*W)
#define CIN_X 256
#define CSKIP 128
#define CCAT 384
#define NPAIR (CCAT/2)   // 192
#define COUT 128
#define NPAIR2 (COUT/2)  // 64
#define OPAD 32          // offset conv padded out-channels (18 -> 32)
#define NPIX (BATCH*HW)
#define EPSV 1e-5f
#define ASTR 72          // halves per smem row (144B)

// ---------------- scratch ------------------------------------------------------
__device__ __align__(16) __half2 g_cat_h2[(size_t)BATCH*NPAIR*HW];
__device__ __align__(16) __half2 g_wpT[9*COUT*NPAIR];     // conv1 w [tap][oc][pair]
__device__ __align__(16) __half2 g_wp2T[9*COUT*NPAIR2];   // def w   [tap][oc][pair]
__device__ __align__(16) __half2 g_wpoT[9*OPAD*NPAIR2];   // off w   [tap][ocp][pair]
__device__ float   g_h[(size_t)BATCH*HW*COUT];            // conv1 out, ch-last fp32
__device__ __align__(16) __half2 g_hh[(size_t)BATCH*HW*NPAIR2]; // h, ch-last fp16
__device__ float   g_off[BATCH*18*HW];
__device__ float   g_y[(size_t)BATCH*HW*COUT];
__device__ float g_sum1[COUT], g_sq1[COUT], g_sum2[COUT], g_sq2[COUT];
__device__ float g_scale1[COUT], g_shift1[COUT], g_scale2[COUT], g_shift2[COUT];

// ---------------- helpers ------------------------------------------------------
__device__ __forceinline__ void ldm_x4(uint32_t& r0, uint32_t& r1, uint32_t& r2,
                                       uint32_t& r3, uint32_t addr) {
    asm volatile("ldmatrix.sync.aligned.m8n8.x4.shared.b16 {%0,%1,%2,%3}, [%4];"
                 : "=r"(r0), "=r"(r1), "=r"(r2), "=r"(r3) : "r"(addr));
}
__device__ __forceinline__ void mma16816(float* c, const uint32_t* a, const uint32_t* b) {
    asm volatile(
        "mma.sync.aligned.m16n8k16.row.col.f32.f16.f16.f32 "
        "{%0,%1,%2,%3}, {%4,%5,%6,%7}, {%8,%9}, {%0,%1,%2,%3};"
        : "+f"(c[0]), "+f"(c[1]), "+f"(c[2]), "+f"(c[3])
        : "r"(a[0]), "r"(a[1]), "r"(a[2]), "r"(a[3]), "r"(b[0]), "r"(b[1]));
}
__device__ __forceinline__ void cp_async4(uint32_t dst, const void* src, int ssize) {
    asm volatile("cp.async.ca.shared.global [%0], [%1], 4, %2;"
                 :: "r"(dst), "l"(src), "r"(ssize) : "memory");
}
__device__ __forceinline__ void cp_async16(uint32_t dst, const void* src) {
    asm volatile("cp.async.cg.shared.global [%0], [%1], 16;"
                 :: "r"(dst), "l"(src) : "memory");
}
__device__ __forceinline__ void cp_async16s(uint32_t dst, const void* src, int ssize) {
    asm volatile("cp.async.cg.shared.global [%0], [%1], 16, %2;"
                 :: "r"(dst), "l"(src), "r"(ssize) : "memory");
}
#define CP_COMMIT() asm volatile("cp.async.commit_group;" ::: "memory")
#define CP_WAIT1()  asm volatile("cp.async.wait_group 1;" ::: "memory")
#define CP_WAIT0()  asm volatile("cp.async.wait_group 0;" ::: "memory")

// ---------------- kernel Z -----------------------------------------------------
__global__ void k_zero() {
    int t = threadIdx.x;
    if (t < COUT) { g_sum1[t]=0.f; g_sq1[t]=0.f; g_sum2[t]=0.f; g_sq2[t]=0.f; }
}

// ---------------- weight packs (transposed: [tap][oc][pair]) --------------------
__global__ void k_wprepT(const float* __restrict__ w) {
    int idx = blockIdx.x * 256 + threadIdx.x;
    if (idx >= 9*COUT*NPAIR) return;
    int p   = idx % NPAIR;
    int oc  = (idx / NPAIR) % COUT;
    int tap = idx / (NPAIR*COUT);
    float w0 = w[((size_t)oc*CCAT + 2*p    )*9 + tap];
    float w1 = w[((size_t)oc*CCAT + 2*p + 1)*9 + tap];
    g_wpT[idx] = __floats2half2_rn(w0, w1);
}
__global__ void k_wprep2T(const float* __restrict__ w) {
    int idx = blockIdx.x * 256 + threadIdx.x;
    if (idx >= 9*COUT*NPAIR2) return;
    int p   = idx % NPAIR2;
    int oc  = (idx / NPAIR2) % COUT;
    int tap = idx / (NPAIR2*COUT);
    float w0 = w[((size_t)oc*COUT + 2*p    )*9 + tap];
    float w1 = w[((size_t)oc*COUT + 2*p + 1)*9 + tap];
    g_wp2T[idx] = __floats2half2_rn(w0, w1);
}
__global__ void k_wprepoT(const float* __restrict__ w) {
    int idx = blockIdx.x * 256 + threadIdx.x;
    if (idx >= 9*OPAD*NPAIR2) return;
    int p   = idx % NPAIR2;
    int oc  = (idx / NPAIR2) % OPAD;
    int tap = idx / (NPAIR2*OPAD);
    float w0 = 0.f, w1 = 0.f;
    if (oc < 18) {
        w0 = w[((size_t)oc*COUT + 2*p    )*9 + tap];
        w1 = w[((size_t)oc*COUT + 2*p + 1)*9 + tap];
    }
    g_wpoT[idx] = __floats2half2_rn(w0, w1);
}

// ---------------- kernel A: upsample + concat (4 pairs / thread) ----------------
__global__ void k_upcat(const float* __restrict__ x, const float* __restrict__ skip) {
    int idx = blockIdx.x * blockDim.x + threadIdx.x;
    if (idx >= BATCH*HW*(NPAIR/4)) return;
    int xc = idx % W;
    int y  = (idx / W) % H;
    int g4 = (idx / HW) % (NPAIR/4);
    int b  = idx / (HW*(NPAIR/4));
    int p0 = g4 * 4;
    size_t obase = ((size_t)b*NPAIR + p0)*HW + y*W + xc;
    if (p0 < CSKIP/2) {
        const float* sp = skip + ((size_t)(b*CSKIP + 2*p0)*HW) + y*W + xc;
        #pragma unroll
        for (int j = 0; j < 4; j++) {
            float v0 = sp[(size_t)(2*j  )*HW];
            float v1 = sp[(size_t)(2*j+1)*HW];
            g_cat_h2[obase + (size_t)j*HW] = __floats2half2_rn(v0, v1);
        }
    } else {
        int ci0 = 2*p0 - CSKIP;
        float fy = (float)y  * (63.0f / 127.0f);
        float fx = (float)xc * (63.0f / 127.0f);
        int y0 = (int)fy, x0 = (int)fx;
        float wy = fy - (float)y0, wx = fx - (float)x0;
        int y1 = min(y0+1, 63), x1 = min(x0+1, 63);
        int i00 = y0*64+x0, i01 = y0*64+x1, i10 = y1*64+x0, i11 = y1*64+x1;
        float w00 = (1.f-wy)*(1.f-wx), w01 = (1.f-wy)*wx;
        float w10 = wy*(1.f-wx), w11 = wy*wx;
        const float* xp = x + (size_t)(b*CIN_X + ci0)*4096;
        #pragma unroll
        for (int j = 0; j < 4; j++) {
            const float* c0p = xp + (size_t)(2*j)*4096;
            const float* c1p = c0p + 4096;
            float v0 = c0p[i00]*w00 + c0p[i01]*w01 + c0p[i10]*w10 + c0p[i11]*w11;
            float v1 = c1p[i00]*w00 + c1p[i01]*w01 + c1p[i10]*w10 + c1p[i11]*w11;
            g_cat_h2[obase + (size_t)j*HW] = __floats2half2_rn(v0, v1);
        }
    }
}

// ---------------- kernel B: conv1 mma, cp.async double-buffered ------------------
#define ABUF_BYTES (128*ASTR*2)   // 18432
#define CONV1_SMEM (4*ABUF_BYTES + COUT*2*4)
__global__ __launch_bounds__(256) void k_conv1_mma() {
    extern __shared__ __align__(16) unsigned char dynsmem[];
    uint32_t smemU = (uint32_t)__cvta_generic_to_shared(dynsmem);
    uint32_t aBuf0 = smemU;
    uint32_t aBuf1 = smemU + ABUF_BYTES;
    uint32_t bBuf0 = smemU + 2*ABUF_BYTES;
    uint32_t bBuf1 = smemU + 3*ABUF_BYTES;
    float* sS = (float*)(dynsmem + 4*ABUF_BYTES);
    float* sQ = sS + COUT;

    int tid = threadIdx.x;
    int wid = tid >> 5, lane = tid & 31;
    int tileX = blockIdx.x * 32, tileY = blockIdx.y * 4;
    int b = blockIdx.z;
    int mBase = (wid & 1) * 64;
    int nBase = (wid >> 1) * 32;
    int grp = lane >> 2, tig = lane & 3;

    uint32_t aOff = (uint32_t)(((mBase + (lane & 15))*ASTR + (lane >> 4)*8) * 2);
    uint32_t bOff = (uint32_t)(((nBase + (lane & 7) + ((lane >> 4) & 1)*8)*ASTR
                                + ((lane >> 3) & 1)*8) * 2);

    float acc[4][4][4];
    #pragma unroll
    for (int mi=0;mi<4;mi++)
        #pragma unroll
        for (int ni=0;ni<4;ni++)
            #pragma unroll
            for (int r=0;r<4;r++) acc[mi][ni][r]=0.f;

    int px_s = tid & 127;
    int half_s = tid >> 7;
    int ly_s = px_s >> 5, lx_s = px_s & 31;
    int ocb = tid >> 3, segb = tid & 7;   // B staging coords (j adds 32 to ocb)

    // prefetch lambda-equivalent
    auto prefetch = [&](int t, uint32_t aB, uint32_t bB) {
        int tap = t / 6, c = t - tap*6;
        int pbase = c * 32;
        int ky = tap/3 - 1, kx = tap - (tap/3)*3 - 1;
        int gy = tileY + ly_s + ky, gx = tileX + lx_s + kx;
        bool valid = (gy >= 0) && (gy < H) && (gx >= 0) && (gx < W);
        int ssz = valid ? 4 : 0;
        const __half2* asrc = g_cat_h2 + (size_t)b*NPAIR*HW + (valid ? gy*W + gx : 0);
        #pragma unroll
        for (int i = 0; i < 16; i++) {
            int pl = i*2 + half_s;
            cp_async4(aB + (uint32_t)((px_s*ASTR + pl*2) * 2),
                      asrc + (size_t)(pbase + pl)*HW, ssz);
        }
        const __half2* bsrc = g_wpT + (size_t)tap*COUT*NPAIR + pbase;
        #pragma unroll
        for (int j = 0; j < 4; j++) {
            int oc = ocb + j*32;
            cp_async16(bB + (uint32_t)((oc*ASTR + segb*8) * 2),
                       bsrc + (size_t)oc*NPAIR + segb*4);
        }
    };

    prefetch(0, aBuf0, bBuf0);
    CP_COMMIT();

    for (int t = 0; t < 54; t++) {
        uint32_t aB = (t & 1) ? aBuf1 : aBuf0;
        uint32_t bB = (t & 1) ? bBuf1 : bBuf0;
        if (t < 53) {
            uint32_t aN = (t & 1) ? aBuf0 : aBuf1;
            uint32_t bN = (t & 1) ? bBuf0 : bBuf1;
            prefetch(t+1, aN, bN);
            CP_COMMIT();
            CP_WAIT1();
        } else {
            CP_WAIT0();
        }
        __syncthreads();
        #pragma unroll
        for (int ks = 0; ks < 4; ks++) {
            uint32_t af[4][4], bf[4][2];
            #pragma unroll
            for (int mi = 0; mi < 4; mi++)
                ldm_x4(af[mi][0], af[mi][1], af[mi][2], af[mi][3],
                       aB + aOff + mi*(16*ASTR*2) + ks*32);
            ldm_x4(bf[0][0], bf[0][1], bf[1][0], bf[1][1], bB + bOff + ks*32);
            ldm_x4(bf[2][0], bf[2][1], bf[3][0], bf[3][1],
                   bB + bOff + 16*ASTR*2 + ks*32);
            #pragma unroll
            for (int mi = 0; mi < 4; mi++)
                #pragma unroll
                for (int ni = 0; ni < 4; ni++)
                    mma16816(acc[mi][ni], af[mi], bf[ni]);
        }
        __syncthreads();
    }

    if (tid < COUT) { sS[tid] = 0.f; sQ[tid] = 0.f; }
    __syncthreads();
    #pragma unroll
    for (int ni = 0; ni < 4; ni++) {
        int oc = nBase + ni*8 + tig*2;
        float s0=0.f,q0=0.f,s1=0.f,q1=0.f;
        #pragma unroll
        for (int mi = 0; mi < 4; mi++) {
            int px0 = mBase + mi*16 + grp;
            int px1 = px0 + 8;
            size_t gp0 = ((size_t)b*HW + (tileY + (px0>>5))*W + tileX + (px0&31))*COUT;
            size_t gp1 = ((size_t)b*HW + (tileY + (px1>>5))*W + tileX + (px1&31))*COUT;
            float a0 = acc[mi][ni][0], a1 = acc[mi][ni][1];
            float a2 = acc[mi][ni][2], a3 = acc[mi][ni][3];
            *(float2*)&g_h[gp0 + oc] = make_float2(a0, a1);
            *(float2*)&g_h[gp1 + oc] = make_float2(a2, a3);
            s0 += a0 + a2; q0 += a0*a0 + a2*a2;
            s1 += a1 + a3; q1 += a1*a1 + a3*a3;
        }
        atomicAdd(&sS[oc], s0);   atomicAdd(&sQ[oc], q0);
        atomicAdd(&sS[oc+1], s1); atomicAdd(&sQ[oc+1], q1);
    }
    __syncthreads();
    if (tid < COUT) {
        atomicAdd(&g_sum1[tid], sS[tid]);
        atomicAdd(&g_sq1[tid], sQ[tid]);
    }
}

// ---------------- kernel C: finalize BN ------------------------------------------
__global__ void k_bnfin(int which, const float* __restrict__ g, const float* __restrict__ bb) {
    int c = threadIdx.x;
    if (c >= COUT) return;
    float s = which ? g_sum2[c] : g_sum1[c];
    float q = which ? g_sq2[c]  : g_sq1[c];
    float m = s / (float)NPIX;
    float v = q / (float)NPIX - m*m;
    float sc = g[c] * rsqrtf(v + EPSV);
    float sh = bb[c] - m * sc;
    if (which) { g_scale2[c] = sc; g_shift2[c] = sh; }
    else       { g_scale1[c] = sc; g_shift1[c] = sh; }
}

// ---------------- kernel D: BN1+ReLU ch-last fp32 -> fp16 -------------------------
__global__ void k_bnrelu1() {
    int idx = blockIdx.x * 256 + threadIdx.x;
    if (idx >= BATCH*HW*NPAIR2) return;
    int p = idx & 63;
    float2 v = *(const float2*)&g_h[(size_t)idx*2];
    float r0 = fmaxf(v.x * g_scale1[2*p]   + g_shift1[2*p],   0.f);
    float r1 = fmaxf(v.y * g_scale1[2*p+1] + g_shift1[2*p+1], 0.f);
    g_hh[idx] = __floats2half2_rn(r0, r1);
}

// ---------------- kernel E: offset conv via mma (oc padded to 32) -----------------
__global__ __launch_bounds__(256) void k_offconv_mma(const float* __restrict__ bias) {
    __shared__ __align__(16) __half sA[2][128*ASTR];
    __shared__ __align__(16) __half sB[2][OPAD*ASTR];
    int tid = threadIdx.x;
    int wid = tid >> 5, lane = tid & 31;
    int tileX = blockIdx.x * 32, tileY = blockIdx.y * 4;
    int b = blockIdx.z;
    int mBase = (wid & 3) * 32;
    int nBase = (wid >> 2) * 16;
    int grp = lane >> 2, tig = lane & 3;

    uint32_t sA_u = (uint32_t)__cvta_generic_to_shared(sA);
    uint32_t sB_u = (uint32_t)__cvta_generic_to_shared(sB);
    uint32_t aOff = (uint32_t)(((mBase + (lane & 15))*ASTR + (lane >> 4)*8) * 2);
    uint32_t bOff = (uint32_t)(((nBase + (lane & 7) + ((lane >> 4) & 1)*8)*ASTR
                                + ((lane >> 3) & 1)*8) * 2);

    float acc[2][2][4];
    #pragma unroll
    for (int mi=0;mi<2;mi++)
        #pragma unroll
        for (int ni=0;ni<2;ni++)
            #pragma unroll
            for (int r=0;r<4;r++) acc[mi][ni][r]=0.f;

    int px_s = tid & 127;
    int half_s = tid >> 7;
    int ly_s = px_s >> 5, lx_s = px_s & 31;
    int ocb = tid >> 3, segb = tid & 7;

    auto prefetch = [&](int t, int buf) {
        int tap = t >> 1, ch = t & 1;
        int pb = ch * 32;
        int ky = tap/3 - 1, kx = tap - (tap/3)*3 - 1;
        int gy = tileY + ly_s + ky, gx = tileX + lx_s + kx;
        bool valid = (gy >= 0) && (gy < H) && (gx >= 0) && (gx < W);
        int ssz = valid ? 16 : 0;
        const __half2* asrc = g_hh + ((size_t)b*HW + (valid ? gy*W + gx : 0))*NPAIR2
                              + pb + half_s*16;
        uint32_t adst = sA_u + buf*(uint32_t)(128*ASTR*2)
                        + (uint32_t)((px_s*ASTR + half_s*32) * 2);
        #pragma unroll
        for (int jj = 0; jj < 4; jj++)
            cp_async16s(adst + jj*16, asrc + jj*4, ssz);
        const __half2* bsrc = g_wpoT + (size_t)tap*OPAD*NPAIR2 + (size_t)ocb*NPAIR2
                              + pb + segb*4;
        cp_async16(sB_u + buf*(uint32_t)(OPAD*ASTR*2)
                   + (uint32_t)((ocb*ASTR + segb*8) * 2), bsrc);
    };

    prefetch(0, 0);
    CP_COMMIT();
    for (int t = 0; t < 18; t++) {
        int buf = t & 1;
        if (t < 17) { prefetch(t+1, buf^1); CP_COMMIT(); CP_WAIT1(); }
        else CP_WAIT0();
        __syncthreads();
        uint32_t aB = sA_u + buf*(uint32_t)(128*ASTR*2);
        uint32_t bB = sB_u + buf*(uint32_t)(OPAD*ASTR*2);
        #pragma unroll
        for (int ks = 0; ks < 4; ks++) {
            uint32_t af[2][4], bf[2][2];
            #pragma unroll
            for (int mi = 0; mi < 2; mi++)
                ldm_x4(af[mi][0], af[mi][1], af[mi][2], af[mi][3],
                       aB + aOff + mi*(16*ASTR*2) + ks*32);
            ldm_x4(bf[0][0], bf[0][1], bf[1][0], bf[1][1], bB + bOff + ks*32);
            #pragma unroll
            for (int mi = 0; mi < 2; mi++)
                #pragma unroll
                for (int ni = 0; ni < 2; ni++)
                    mma16816(acc[mi][ni], af[mi], bf[ni]);
        }
        __syncthreads();
    }

    #pragma unroll
    for (int ni = 0; ni < 2; ni++) {
        int oc = nBase + ni*8 + tig*2;
        if (oc >= 18) continue;
        float b0 = bias[oc];
        float b1 = (oc + 1 < 18) ? bias[oc+1] : 0.f;
        #pragma unroll
        for (int mi = 0; mi < 2; mi++) {
            int px0 = mBase + mi*16 + grp;
            int px1 = px0 + 8;
            int y0 = tileY + (px0>>5), x0 = tileX + (px0&31);
            int y1 = tileY + (px1>>5), x1 = tileX + (px1&31);
            g_off[((size_t)(b*18 + oc)*HW) + y0*W + x0] = acc[mi][ni][0] + b0;
            g_off[((size_t)(b*18 + oc)*HW) + y1*W + x1] = acc[mi][ni][2] + b0;
            if (oc + 1 < 18) {
                g_off[((size_t)(b*18 + oc + 1)*HW) + y0*W + x0] = acc[mi][ni][1] + b1;
                g_off[((size_t)(b*18 + oc + 1)*HW) + y1*W + x1] = acc[mi][ni][3] + b1;
            }
        }
    }
}

// ---------------- kernel F: deformable conv via mma -------------------------------
__global__ __launch_bounds__(256) void k_deform_mma(const float* __restrict__ db) {
    __shared__ __align__(16) __half sA[128*ASTR];
    __shared__ __align__(16) __half sB[128*ASTR];
    __shared__ int   sOff[4][128];
    __shared__ float sWgt[4][128];
    __shared__ float sS[COUT], sQ[COUT];
    int tid = threadIdx.x;
    int wid = tid >> 5, lane = tid & 31;
    int tileX = blockIdx.x * 32, tileY = blockIdx.y * 4;
    int b = blockIdx.z;
    int mBase = (wid & 1) * 64;
    int nBase = (wid >> 1) * 32;
    int grp = lane >> 2, tig = lane & 3;

    uint32_t sA_u = (uint32_t)__cvta_generic_to_shared(sA);
    uint32_t sB_u = (uint32_t)__cvta_generic_to_shared(sB);
    uint32_t aAddr = sA_u + (uint32_t)(((mBase + (lane & 15))*ASTR + (lane >> 4)*8) * 2);
    uint32_t bAddr = sB_u + (uint32_t)(((nBase + (lane & 7) + ((lane >> 4) & 1)*8)*ASTR
                                        + ((lane >> 3) & 1)*8) * 2);

    float acc[4][4][4];
    #pragma unroll
    for (int mi=0;mi<4;mi++)
        #pragma unroll
        for (int ni=0;ni<4;ni++)
            #pragma unroll
            for (int r=0;r<4;r++) acc[mi][ni][r]=0.f;

    int px_s = tid & 127;
    int half_s = tid >> 7;
    int ocb = tid >> 3, segb = tid & 7;

    for (int tap = 0; tap < 9; tap++) {
        if (tid < 128) {
            int ly = tid >> 5, lx = tid & 31;
            int y = tileY + ly, x = tileX + lx;
            float dy = g_off[((size_t)(b*18 + 2*tap    )*HW) + y*W + x];
            float dx = g_off[((size_t)(b*18 + 2*tap + 1)*HW) + y*W + x];
            float py = (float)y + (float)(tap/3 - 1) + dy;
            float pxx = (float)x + (float)(tap%3 - 1) + dx;
            float y0f = floorf(py), x0f = floorf(pxx);
            float wy = py - y0f, wx = pxx - x0f;
            int yi = (int)y0f, xi = (int)x0f;
            bool yv0 = (yi >= 0) && (yi < H);
            bool yv1 = (yi+1 >= 0) && (yi+1 < H);
            bool xv0 = (xi >= 0) && (xi < W);
            bool xv1 = (xi+1 >= 0) && (xi+1 < W);
            int yc0 = min(max(yi, 0), H-1), yc1 = min(max(yi+1, 0), H-1);
            int xc0 = min(max(xi, 0), W-1), xc1 = min(max(xi+1, 0), W-1);
            int base = b*HW;
            sOff[0][tid] = (base + yc0*W + xc0) << 6;
            sOff[1][tid] = (base + yc0*W + xc1) << 6;
            sOff[2][tid] = (base + yc1*W + xc0) << 6;
            sOff[3][tid] = (base + yc1*W + xc1) << 6;
            sWgt[0][tid] = (yv0 && xv0) ? (1.f-wy)*(1.f-wx) : 0.f;
            sWgt[1][tid] = (yv0 && xv1) ? (1.f-wy)*wx       : 0.f;
            sWgt[2][tid] = (yv1 && xv0) ? wy*(1.f-wx)       : 0.f;
            sWgt[3][tid] = (yv1 && xv1) ? wy*wx             : 0.f;
        }
        __syncthreads();

        int o0 = sOff[0][px_s], o1 = sOff[1][px_s], o2 = sOff[2][px_s], o3 = sOff[3][px_s];
        float w0 = sWgt[0][px_s], w1 = sWgt[1][px_s], w2 = sWgt[2][px_s], w3 = sWgt[3][px_s];

        for (int c0 = 0; c0 < COUT; c0 += 64) {
            // B via cp.async from transposed pack
            const __half2* bsrc = g_wp2T + (size_t)tap*COUT*NPAIR2 + (c0 >> 1);
            #pragma unroll
            for (int j = 0; j < 4; j++) {
                int oc = ocb + j*32;
                cp_async16(sB_u + (uint32_t)((oc*ASTR + segb*8) * 2),
                           bsrc + (size_t)oc*NPAIR2 + segb*4);
            }
            CP_COMMIT();

            int pb = (c0 >> 1) + half_s*16;
            const uint4* p0 = (const uint4*)(g_hh + o0 + pb);
            const uint4* p1 = (const uint4*)(g_hh + o1 + pb);
            const uint4* p2 = (const uint4*)(g_hh + o2 + pb);
            const uint4* p3 = (const uint4*)(g_hh + o3 + pb);
            #pragma unroll
            for (int j = 0; j < 4; j++) {
                uint4 q0 = p0[j], q1 = p1[j], q2 = p2[j], q3 = p3[j];
                uint32_t res[4];
                const uint32_t* a0 = (const uint32_t*)&q0;
                const uint32_t* a1 = (const uint32_t*)&q1;
                const uint32_t* a2 = (const uint32_t*)&q2;
                const uint32_t* a3 = (const uint32_t*)&q3;
                #pragma unroll
                for (int e = 0; e < 4; e++) {
                    float2 f0 = __half22float2(*(__half2*)&a0[e]);
                    float2 f1 = __half22float2(*(__half2*)&a1[e]);
                    float2 f2 = __half22float2(*(__half2*)&a2[e]);
                    float2 f3 = __half22float2(*(__half2*)&a3[e]);
                    float rx = w0*f0.x + w1*f1.x + w2*f2.x + w3*f3.x;
                    float ry = w0*f0.y + w1*f1.y + w2*f2.y + w3*f3.y;
                    __half2 hv = __floats2half2_rn(rx, ry);
                    res[e] = *(uint32_t*)&hv;
                }
                *(uint4*)&sA[px_s*ASTR + (half_s*16 + j*4)*2] = *(uint4*)res;
            }
            CP_WAIT0();
            __syncthreads();
            #pragma unroll
            for (int ks = 0; ks < 4; ks++) {
                uint32_t af[4][4], bf[4][2];
                #pragma unroll
                for (int mi = 0; mi < 4; mi++)
                    ldm_x4(af[mi][0], af[mi][1], af[mi][2], af[mi][3],
                           aAddr + mi*(16*ASTR*2) + ks*32);
                ldm_x4(bf[0][0], bf[0][1], bf[1][0], bf[1][1], bAddr + ks*32);
                ldm_x4(bf[2][0], bf[2][1], bf[3][0], bf[3][1],
                       bAddr + 16*ASTR*2 + ks*32);
                #pragma unroll
                for (int mi = 0; mi < 4; mi++)
                    #pragma unroll
                    for (int ni = 0; ni < 4; ni++)
                        mma16816(acc[mi][ni], af[mi], bf[ni]);
            }
            __syncthreads();
        }
    }

    if (tid < COUT) { sS[tid] = 0.f; sQ[tid] = 0.f; }
    __syncthreads();
    #pragma unroll
    for (int ni = 0; ni < 4; ni++) {
        int oc = nBase + ni*8 + tig*2;
        float b0 = db[oc], b1 = db[oc+1];
        float s0=0.f,q0=0.f,s1=0.f,q1=0.f;
        #pragma unroll
        for (int mi = 0; mi < 4; mi++) {
            int px0 = mBase + mi*16 + grp;
            int px1 = px0 + 8;
            size_t gp0 = ((size_t)b*HW + (tileY + (px0>>5))*W + tileX + (px0&31))*COUT;
            size_t gp1 = ((size_t)b*HW + (tileY + (px1>>5))*W + tileX + (px1&31))*COUT;
            float a0 = acc[mi][ni][0] + b0, a1 = acc[mi][ni][1] + b1;
            float a2 = acc[mi][ni][2] + b0, a3 = acc[mi][ni][3] + b1;
            *(float2*)&g_y[gp0 + oc] = make_float2(a0, a1);
            *(float2*)&g_y[gp1 + oc] = make_float2(a2, a3);
            s0 += a0 + a2; q0 += a0*a0 + a2*a2;
            s1 += a1 + a3; q1 += a1*a1 + a3*a3;
        }
        atomicAdd(&sS[oc], s0);   atomicAdd(&sQ[oc], q0);
        atomicAdd(&sS[oc+1], s1); atomicAdd(&sQ[oc+1], q1);
    }
    __syncthreads();
    if (tid < COUT) {
        atomicAdd(&g_sum2[tid], sS[tid]);
        atomicAdd(&g_sq2[tid], sQ[tid]);
    }
}

// ---------------- kernel H: BN2+ReLU ch-last -> planar out ------------------------
__global__ __launch_bounds__(256) void k_bnrelu2(float* __restrict__ out) {
    __shared__ float s[32][129];
    int tid = threadIdx.x;
    int px0 = blockIdx.x * 32;
    int b = blockIdx.y;
    #pragma unroll
    for (int j = 0; j < 16; j++) {
        int idx = tid + j*256;
        int pxl = idx >> 7, c = idx & 127;
        s[pxl][c] = g_y[((size_t)b*HW + px0 + pxl)*COUT + c];
    }
    __syncthreads();
    #pragma unroll
    for (int j = 0; j < 16; j++) {
        int idx = tid + j*256;
        int c = idx >> 5, pxl = idx & 31;
        float v = s[pxl][c] * g_scale2[c] + g_shift2[c];
        out[((size_t)(b*COUT + c)*HW) + px0 + pxl] = fmaxf(v, 0.f);
    }
}

// ---------------- launch -----------------------------------------------------------
extern "C" void kernel_launch(void* const* d_in, const int* in_sizes, int n_in,
                              void* d_out, int out_size) {
    const float* x       = (const float*)d_in[0];
    const float* skip    = (const float*)d_in[1];
    const float* conv1_w = (const float*)d_in[2];
    const float* bn1_g   = (const float*)d_in[3];
    const float* bn1_b   = (const float*)d_in[4];
    const float* off_w   = (const float*)d_in[5];
    const float* off_b   = (const float*)d_in[6];
    const float* def_w   = (const float*)d_in[7];
    const float* def_b   = (const float*)d_in[8];
    const float* bn2_g   = (const float*)d_in[9];
    const float* bn2_b   = (const float*)d_in[10];
    float* out = (float*)d_out;

    static bool attrDone = false;
    if (!attrDone) {
        cudaFuncSetAttribute(k_conv1_mma,
                             cudaFuncAttributeMaxDynamicSharedMemorySize, CONV1_SMEM);
        attrDone = true;
    }

    k_zero<<<1, 256>>>();
    k_wprepT<<<(9*COUT*NPAIR + 255)/256, 256>>>(conv1_w);
    k_wprep2T<<<(9*COUT*NPAIR2 + 255)/256, 256>>>(def_w);
    k_wprepoT<<<(9*OPAD*NPAIR2 + 255)/256, 256>>>(off_w);

    int nup = BATCH*HW*(NPAIR/4);
    k_upcat<<<(nup + 255)/256, 256>>>(x, skip);

    k_conv1_mma<<<dim3(W/32, H/4, BATCH), 256, CONV1_SMEM>>>();
    k_bnfin<<<1, COUT>>>(0, bn1_g, bn1_b);

    int nhp = BATCH*HW*NPAIR2;
    k_bnrelu1<<<(nhp + 255)/256, 256>>>();

    k_offconv_mma<<<dim3(W/32, H/4, BATCH), 256>>>(off_b);

    k_deform_mma<<<dim3(W/32, H/4, BATCH), 256>>>(def_b);
    k_bnfin<<<1, COUT>>>(1, bn2_g, bn2_b);

    k_bnrelu2<<<dim3(HW/32, BATCH), 256>>>(out);
}